// round 15
// baseline (speedup 1.0000x reference)
#include <cuda_runtime.h>
#include <cstdint>

// ============================================================================
// Clebsch-Gordan tensor product, MAXL=5, TAUS=16, BATCH=256.
// R15 = R14 (32 merged (l1,l2)-groups, scalar FFMA with compile-time CG,
//       64-reg budget, SMEM staging, TMA bulk copy-out, wait_group.read,
//       (0,0) direct-store path) + producer/consumer epilogue barrier:
//       warps 1-7 bar.arrive and EXIT after their stores; warp 0 bar.sync,
//       lane 0 issues TMA + drains. 7/8 of warps stop occupying issue slots
//       during the per-block epilogue.
// Evidence basis: kernel sits at the HBM write-path floor (~4.6 TB/s pure
// writes); only epilogue/tail trimming can still move it.
// ============================================================================

#define NGRP 32
// X(G, L1, L2, LA, LB): block handles outputs l in [LA..LB] of pair (L1,L2).
// Heavy-first order.
#define GROUPS(X) \
X(0,3,1,2,4)  X(1,5,5,4,5)  X(2,5,4,4,5)  X(3,5,3,4,5)  X(4,5,2,4,5) \
X(5,5,1,4,5)  X(6,4,4,4,5)  X(7,4,3,4,5)  X(8,4,2,4,5)  X(9,4,1,4,5) \
X(10,3,3,4,5) X(11,3,2,4,5) X(12,5,5,0,3) X(13,4,4,0,3) X(14,3,3,0,3) \
X(15,2,2,3,4) X(16,5,4,1,3) X(17,4,3,1,3) X(18,3,2,1,3) X(19,2,1,1,3) \
X(20,5,3,2,3) X(21,4,2,2,3) X(22,5,0,5,5) X(23,4,0,4,4) X(24,2,2,0,2) \
X(25,1,1,0,2) X(26,5,2,3,3) X(27,4,1,3,3) X(28,3,0,3,3) X(29,2,0,2,2) \
X(30,1,0,1,1) X(31,0,0,0,0)

// ---------------------------------------------------------------------------
// Compile-time CG coefficients (exact fp64 factorials, Newton sqrt).
// ---------------------------------------------------------------------------
__host__ __device__ constexpr double cfact(int n) {
    double r = 1.0;
    for (int i = 2; i <= n; i++) r *= (double)i;
    return r;
}
__host__ __device__ constexpr double csqrt(double x) {
    if (x <= 0.0) return 0.0;
    double g = x > 1.0 ? x : 1.0;
    for (int i = 0; i < 200; i++) g = 0.5 * (g + x / g);
    return g;
}
__host__ __device__ constexpr double cg_cd(int l1, int l2, int l, int m1, int m2) {
    int m = m1 + m2;
    if (m < -l || m > l) return 0.0;
    if (l < (l1 > l2 ? l1 - l2 : l2 - l1) || l > l1 + l2) return 0.0;
    double pref = (double)(2 * l + 1)
        * cfact(l + l1 - l2) * cfact(l - l1 + l2) * cfact(l1 + l2 - l)
        / cfact(l1 + l2 + l + 1);
    pref *= cfact(l + m) * cfact(l - m)
          * cfact(l1 - m1) * cfact(l1 + m1)
          * cfact(l2 - m2) * cfact(l2 + m2);
    int kmin = 0;
    if (-(l - l2 + m1) > kmin) kmin = -(l - l2 + m1);
    if (-(l - l1 - m2) > kmin) kmin = -(l - l1 - m2);
    int kmax = l1 + l2 - l;
    if (l1 - m1 < kmax) kmax = l1 - m1;
    if (l2 + m2 < kmax) kmax = l2 + m2;
    double s = 0.0;
    for (int k = kmin; k <= kmax; k++) {
        double d = cfact(k) * cfact(l1 + l2 - l - k) * cfact(l1 - m1 - k)
                 * cfact(l2 + m2 - k) * cfact(l - l2 + m1 + k)
                 * cfact(l - l1 - m2 + k);
        s += (k & 1) ? (-1.0 / d) : (1.0 / d);
    }
    return csqrt(pref) * s;
}

// ---------------------------------------------------------------------------
// Compile-time output layout (reference _TRIPLES order: l1 asc, l2 asc, l asc)
// ---------------------------------------------------------------------------
__host__ __device__ constexpr int LMX(int a) { return a > 5 ? 5 : a; }
__host__ __device__ constexpr int CNT(int l) {
    int c = 0;
    for (int l1 = 0; l1 <= 5; l1++)
        for (int l2 = 0; l2 <= l1; l2++)
            for (int lo = l1 - l2; lo <= LMX(l1 + l2); lo++)
                if (lo == l) c++;
    return c;
}
__host__ __device__ constexpr long BASE(int l) {   // float2 offset of out[l]
    long b = 0;
    for (int x = 0; x < l; x++) b += 65536L * CNT(x) * (2 * x + 1);
    return b;
}
__host__ __device__ constexpr int FIDX(int L1, int L2, int l) {
    int c = 0;
    for (int l1 = 0; l1 <= 5; l1++)
        for (int l2 = 0; l2 <= l1; l2++)
            for (int lo = l1 - l2; lo <= LMX(l1 + l2); lo++)
                if (lo == l) { if (l1 == L1 && l2 == L2) return c; c++; }
    return 0;
}

template <int L1, int L2, int LA, int LB>
struct GrpOff {
    static constexpr int NL = LB - LA + 1;
    long dbase[NL];   // out[l] section base + fragment channel offset (float2)
    long bstr[NL];    // per-batch stride = 256*CNT(l)*(2l+1)
    int  sbase[NL];   // smem section base (float2)
    constexpr GrpOff() : dbase(), bstr(), sbase() {
        int off = 0;
        for (int lu = 0; lu < NL; lu++) {
            int l = LA + lu, D = 2 * l + 1;
            dbase[lu] = BASE(l) + 256L * FIDX(L1, L2, l) * D;
            bstr[lu]  = 256L * CNT(l) * D;
            sbase[lu] = off;
            off += 256 * D;
        }
    }
};
template <int L1, int L2, int LA, int LB>
__device__ constexpr GrpOff<L1, L2, LA, LB> g_off{};

template <int L1, int L2, int LA, int LB>
struct CGSet {
    float c[LB - LA + 1][2 * LB + 1][2 * L1 + 1];
    constexpr CGSet() : c() {
        for (int lu = 0; lu <= LB - LA; lu++) {
            int l = LA + lu;
            for (int mi = 0; mi < 2 * l + 1; mi++)
                for (int k1 = 0; k1 < 2 * L1 + 1; k1++) {
                    int m1 = k1 - L1;
                    int m2 = (mi - l) - m1;
                    c[lu][mi][k1] = (m2 >= -L2 && m2 <= L2)
                                  ? (float)cg_cd(L1, L2, l, m1, m2) : 0.0f;
                }
        }
    }
};
template <int L1, int L2, int LA, int LB>
__device__ constexpr CGSet<L1, L2, LA, LB> g_cgs{};

// ---------------------------------------------------------------------------
// Group body. thread t = channel pair (i=t>>4, j=t&15), batch b.
// m outer, k1 inner: products u,v computed once, shared by all l >= |m| via
// FFMA with compile-time immediate CG weight. SMEM staging.
// Epilogue: warps 1-7 bar.arrive + exit; warp 0 bar.sync, lane 0 issues the
// TMA bulk copies and drains with wait_group.read semantics.
// (0,0) group: direct coalesced store, no barrier at all.
// ---------------------------------------------------------------------------
template <int L1, int L2, int LA, int LB>
__device__ __forceinline__ void grp_body(
    const float2* __restrict__ act1, const float2* __restrict__ act2,
    float2* __restrict__ out, int b, float2* __restrict__ sh)
{
    constexpr int D1 = 2 * L1 + 1;
    constexpr int D2 = 2 * L2 + 1;
    constexpr int NL = LB - LA + 1;
    constexpr bool RES1 = (2 * (D1 + D2) + 2 * NL) <= 50;
    constexpr bool DIRECT = (NL == 1 && LB == 0);   // (0,0) only

    const int t = threadIdx.x;
    const int i = t >> 4;
    const int j = t & 15;

    float2 a2r[D2];
    const float2* p2 = act2 + (b * 16 + j) * D2;
#pragma unroll
    for (int k = 0; k < D2; k++) a2r[k] = __ldg(p2 + k);

    const float2* p1 = act1 + (b * 16 + i) * D1;
    float2 a1r[RES1 ? D1 : 1];
    if (RES1) {
#pragma unroll
        for (int k = 0; k < D1; k++) a1r[k] = __ldg(p1 + k);
    }

    if (DIRECT) {
        // (0,0): D=1, identity mapping -> direct coalesced store, no SMEM.
        const float2 v1 = RES1 ? a1r[0] : __ldg(p1);
        const float2 v2 = a2r[0];
        const float C = g_cgs<L1, L2, LA, LB>.c[0][0][0];
        float2* dst = out + g_off<L1, L2, LA, LB>.dbase[0]
                    + (long)b * g_off<L1, L2, LA, LB>.bstr[0];
        dst[t] = make_float2(
            C * fmaf(v1.x, v2.x, -(v1.y * v2.y)),
            C * fmaf(v1.x, v2.y, v1.y * v2.x));
        return;
    }

#pragma unroll
    for (int m = -LB; m <= LB; m++) {
        const int absm = m < 0 ? -m : m;
        const int k1lo = (m + L1 - L2) > 0 ? (m + L1 - L2) : 0;
        const int k1hi = (m + L1 + L2) < (2 * L1) ? (m + L1 + L2) : (2 * L1);

        float aR[NL], aI[NL];
#pragma unroll
        for (int lu = 0; lu < NL; lu++) { aR[lu] = 0.0f; aI[lu] = 0.0f; }

#pragma unroll
        for (int k1 = k1lo; k1 <= k1hi; k1++) {
            const float2 v1 = RES1 ? a1r[k1] : __ldg(p1 + k1);
            const float2 v2 = a2r[m - (k1 - L1) + L2];
            const float u = fmaf(v1.x, v2.x, -(v1.y * v2.y));
            const float v = fmaf(v1.x, v2.y, v1.y * v2.x);
#pragma unroll
            for (int lu = 0; lu < NL; lu++) {
                const int l = LA + lu;
                if (l >= absm) {
                    const float C = g_cgs<L1, L2, LA, LB>.c[lu][m + l][k1];
                    if (C != 0.0f) {           // folds at compile time
                        aR[lu] = fmaf(C, u, aR[lu]);
                        aI[lu] = fmaf(C, v, aI[lu]);
                    }
                }
            }
        }
#pragma unroll
        for (int lu = 0; lu < NL; lu++) {
            const int l = LA + lu;
            if (l >= absm)
                sh[g_off<L1, L2, LA, LB>.sbase[lu] + t * (2 * l + 1) + (m + l)]
                    = make_float2(aR[lu], aI[lu]);
        }
    }

    // --- Producer/consumer epilogue barrier ---
    // Warps 1-7: signal arrival (making their STS visible to the bar.sync
    // waiters per PTX barrier memory semantics) and exit immediately.
    // Warp 0: full sync, then lane 0 issues TMA bulk copies and drains.
    if (t >= 32) {
        asm volatile("bar.arrive 0, 256;" ::: "memory");
        return;
    }
    asm volatile("bar.sync 0, 256;" ::: "memory");

    if (t == 0) {
        asm volatile("fence.proxy.async.shared::cta;" ::: "memory");
#pragma unroll
        for (int lu = 0; lu < NL; lu++) {
            const int l = LA + lu, D = 2 * l + 1;
            float2* dst = out + g_off<L1, L2, LA, LB>.dbase[lu]
                        + (long)b * g_off<L1, L2, LA, LB>.bstr[lu];
            uint32_t saddr;
            asm("{ .reg .u64 tt; cvta.to.shared.u64 tt, %1; cvt.u32.u64 %0, tt; }"
                : "=r"(saddr)
                : "l"(sh + g_off<L1, L2, LA, LB>.sbase[lu]));
            asm volatile(
                "cp.async.bulk.global.shared::cta.bulk_group [%0], [%1], %2;"
                :: "l"((unsigned long long)(uintptr_t)dst),
                   "r"(saddr), "r"(2048 * D)
                : "memory");
        }
        asm volatile("cp.async.bulk.commit_group;" ::: "memory");
        // Only the SMEM source reads must finish before the CTA may retire;
        // grid completion guarantees global visibility of the writes.
        asm volatile("cp.async.bulk.wait_group.read 0;" ::: "memory");
    }
}

__global__ void __launch_bounds__(256, 4) cg_main_kernel(
    const float* __restrict__ a0, const float* __restrict__ a1,
    const float* __restrict__ a2, const float* __restrict__ a3,
    const float* __restrict__ a4, const float* __restrict__ a5,
    float2* __restrict__ out)
{
    __shared__ alignas(16) float2 sh[21 * 256];   // max sum(2l+1)=21 -> 43KB
    const int b = blockIdx.x;

    switch (blockIdx.y) {
#define GCASE(G,L1,L2,LA,LB)                                                  \
    case G:                                                                   \
        grp_body<L1, L2, LA, LB>((const float2*)a##L1, (const float2*)a##L2,  \
                                 out, b, sh);                                 \
        break;
    GROUPS(GCASE)
#undef GCASE
    default: break;
    }
}

// ---------------------------------------------------------------------------
// Host side
// ---------------------------------------------------------------------------
extern "C" void kernel_launch(void* const* d_in, const int* in_sizes, int n_in,
                              void* d_out, int out_size)
{
    (void)in_sizes; (void)n_in; (void)out_size;

    cg_main_kernel<<<dim3(256, NGRP), 256>>>(
        (const float*)d_in[0], (const float*)d_in[1], (const float*)d_in[2],
        (const float*)d_in[3], (const float*)d_in[4], (const float*)d_in[5],
        (float2*)d_out);
}

// round 16
// speedup vs baseline: 1.3630x; 1.3630x over previous
#include <cuda_runtime.h>
#include <cstdint>

// ============================================================================
// Clebsch-Gordan tensor product, MAXL=5, TAUS=16, BATCH=256.
// R16 = R14 (best: 32 merged (l1,l2)-groups, scalar FFMA with compile-time CG,
//       64-reg budget, SMEM staging, TMA bulk copy-out, wait_group.read,
//       (0,0) direct-store path) + L2::evict_first cache policy on the bulk
//       copies: output is write-once-never-read, so its lines should stream
//       through L2 at lowest retention priority instead of polluting it.
// Evidence: ncu DRAM bytes (~181MB) < output size (240MB) at kernel end ->
// the kernel paces on the L2 write-allocate path, the targeted resource here.
// ============================================================================

#define NGRP 32
// X(G, L1, L2, LA, LB): block handles outputs l in [LA..LB] of pair (L1,L2).
// Heavy-first order.
#define GROUPS(X) \
X(0,3,1,2,4)  X(1,5,5,4,5)  X(2,5,4,4,5)  X(3,5,3,4,5)  X(4,5,2,4,5) \
X(5,5,1,4,5)  X(6,4,4,4,5)  X(7,4,3,4,5)  X(8,4,2,4,5)  X(9,4,1,4,5) \
X(10,3,3,4,5) X(11,3,2,4,5) X(12,5,5,0,3) X(13,4,4,0,3) X(14,3,3,0,3) \
X(15,2,2,3,4) X(16,5,4,1,3) X(17,4,3,1,3) X(18,3,2,1,3) X(19,2,1,1,3) \
X(20,5,3,2,3) X(21,4,2,2,3) X(22,5,0,5,5) X(23,4,0,4,4) X(24,2,2,0,2) \
X(25,1,1,0,2) X(26,5,2,3,3) X(27,4,1,3,3) X(28,3,0,3,3) X(29,2,0,2,2) \
X(30,1,0,1,1) X(31,0,0,0,0)

// ---------------------------------------------------------------------------
// Compile-time CG coefficients (exact fp64 factorials, Newton sqrt).
// ---------------------------------------------------------------------------
__host__ __device__ constexpr double cfact(int n) {
    double r = 1.0;
    for (int i = 2; i <= n; i++) r *= (double)i;
    return r;
}
__host__ __device__ constexpr double csqrt(double x) {
    if (x <= 0.0) return 0.0;
    double g = x > 1.0 ? x : 1.0;
    for (int i = 0; i < 200; i++) g = 0.5 * (g + x / g);
    return g;
}
__host__ __device__ constexpr double cg_cd(int l1, int l2, int l, int m1, int m2) {
    int m = m1 + m2;
    if (m < -l || m > l) return 0.0;
    if (l < (l1 > l2 ? l1 - l2 : l2 - l1) || l > l1 + l2) return 0.0;
    double pref = (double)(2 * l + 1)
        * cfact(l + l1 - l2) * cfact(l - l1 + l2) * cfact(l1 + l2 - l)
        / cfact(l1 + l2 + l + 1);
    pref *= cfact(l + m) * cfact(l - m)
          * cfact(l1 - m1) * cfact(l1 + m1)
          * cfact(l2 - m2) * cfact(l2 + m2);
    int kmin = 0;
    if (-(l - l2 + m1) > kmin) kmin = -(l - l2 + m1);
    if (-(l - l1 - m2) > kmin) kmin = -(l - l1 - m2);
    int kmax = l1 + l2 - l;
    if (l1 - m1 < kmax) kmax = l1 - m1;
    if (l2 + m2 < kmax) kmax = l2 + m2;
    double s = 0.0;
    for (int k = kmin; k <= kmax; k++) {
        double d = cfact(k) * cfact(l1 + l2 - l - k) * cfact(l1 - m1 - k)
                 * cfact(l2 + m2 - k) * cfact(l - l2 + m1 + k)
                 * cfact(l - l1 - m2 + k);
        s += (k & 1) ? (-1.0 / d) : (1.0 / d);
    }
    return csqrt(pref) * s;
}

// ---------------------------------------------------------------------------
// Compile-time output layout (reference _TRIPLES order: l1 asc, l2 asc, l asc)
// ---------------------------------------------------------------------------
__host__ __device__ constexpr int LMX(int a) { return a > 5 ? 5 : a; }
__host__ __device__ constexpr int CNT(int l) {
    int c = 0;
    for (int l1 = 0; l1 <= 5; l1++)
        for (int l2 = 0; l2 <= l1; l2++)
            for (int lo = l1 - l2; lo <= LMX(l1 + l2); lo++)
                if (lo == l) c++;
    return c;
}
__host__ __device__ constexpr long BASE(int l) {   // float2 offset of out[l]
    long b = 0;
    for (int x = 0; x < l; x++) b += 65536L * CNT(x) * (2 * x + 1);
    return b;
}
__host__ __device__ constexpr int FIDX(int L1, int L2, int l) {
    int c = 0;
    for (int l1 = 0; l1 <= 5; l1++)
        for (int l2 = 0; l2 <= l1; l2++)
            for (int lo = l1 - l2; lo <= LMX(l1 + l2); lo++)
                if (lo == l) { if (l1 == L1 && l2 == L2) return c; c++; }
    return 0;
}

template <int L1, int L2, int LA, int LB>
struct GrpOff {
    static constexpr int NL = LB - LA + 1;
    long dbase[NL];   // out[l] section base + fragment channel offset (float2)
    long bstr[NL];    // per-batch stride = 256*CNT(l)*(2l+1)
    int  sbase[NL];   // smem section base (float2)
    constexpr GrpOff() : dbase(), bstr(), sbase() {
        int off = 0;
        for (int lu = 0; lu < NL; lu++) {
            int l = LA + lu, D = 2 * l + 1;
            dbase[lu] = BASE(l) + 256L * FIDX(L1, L2, l) * D;
            bstr[lu]  = 256L * CNT(l) * D;
            sbase[lu] = off;
            off += 256 * D;
        }
    }
};
template <int L1, int L2, int LA, int LB>
__device__ constexpr GrpOff<L1, L2, LA, LB> g_off{};

template <int L1, int L2, int LA, int LB>
struct CGSet {
    float c[LB - LA + 1][2 * LB + 1][2 * L1 + 1];
    constexpr CGSet() : c() {
        for (int lu = 0; lu <= LB - LA; lu++) {
            int l = LA + lu;
            for (int mi = 0; mi < 2 * l + 1; mi++)
                for (int k1 = 0; k1 < 2 * L1 + 1; k1++) {
                    int m1 = k1 - L1;
                    int m2 = (mi - l) - m1;
                    c[lu][mi][k1] = (m2 >= -L2 && m2 <= L2)
                                  ? (float)cg_cd(L1, L2, l, m1, m2) : 0.0f;
                }
        }
    }
};
template <int L1, int L2, int LA, int LB>
__device__ constexpr CGSet<L1, L2, LA, LB> g_cgs{};

// ---------------------------------------------------------------------------
// Group body. thread t = channel pair (i=t>>4, j=t&15), batch b.
// m outer, k1 inner: products u,v computed once, shared by all l >= |m| via
// FFMA with compile-time immediate CG weight. SMEM staging; TMA bulk
// copy-out with L2::evict_first policy; wait_group.read drain.
// (0,0) group: direct coalesced store.
// ---------------------------------------------------------------------------
template <int L1, int L2, int LA, int LB>
__device__ __forceinline__ void grp_body(
    const float2* __restrict__ act1, const float2* __restrict__ act2,
    float2* __restrict__ out, int b, float2* __restrict__ sh)
{
    constexpr int D1 = 2 * L1 + 1;
    constexpr int D2 = 2 * L2 + 1;
    constexpr int NL = LB - LA + 1;
    constexpr bool RES1 = (2 * (D1 + D2) + 2 * NL) <= 50;
    constexpr bool DIRECT = (NL == 1 && LB == 0);   // (0,0) only

    const int t = threadIdx.x;
    const int i = t >> 4;
    const int j = t & 15;

    float2 a2r[D2];
    const float2* p2 = act2 + (b * 16 + j) * D2;
#pragma unroll
    for (int k = 0; k < D2; k++) a2r[k] = __ldg(p2 + k);

    const float2* p1 = act1 + (b * 16 + i) * D1;
    float2 a1r[RES1 ? D1 : 1];
    if (RES1) {
#pragma unroll
        for (int k = 0; k < D1; k++) a1r[k] = __ldg(p1 + k);
    }

    if (DIRECT) {
        // (0,0): D=1, identity mapping -> direct coalesced store, no SMEM.
        const float2 v1 = RES1 ? a1r[0] : __ldg(p1);
        const float2 v2 = a2r[0];
        const float C = g_cgs<L1, L2, LA, LB>.c[0][0][0];
        float2* dst = out + g_off<L1, L2, LA, LB>.dbase[0]
                    + (long)b * g_off<L1, L2, LA, LB>.bstr[0];
        dst[t] = make_float2(
            C * fmaf(v1.x, v2.x, -(v1.y * v2.y)),
            C * fmaf(v1.x, v2.y, v1.y * v2.x));
        return;
    }

#pragma unroll
    for (int m = -LB; m <= LB; m++) {
        const int absm = m < 0 ? -m : m;
        const int k1lo = (m + L1 - L2) > 0 ? (m + L1 - L2) : 0;
        const int k1hi = (m + L1 + L2) < (2 * L1) ? (m + L1 + L2) : (2 * L1);

        float aR[NL], aI[NL];
#pragma unroll
        for (int lu = 0; lu < NL; lu++) { aR[lu] = 0.0f; aI[lu] = 0.0f; }

#pragma unroll
        for (int k1 = k1lo; k1 <= k1hi; k1++) {
            const float2 v1 = RES1 ? a1r[k1] : __ldg(p1 + k1);
            const float2 v2 = a2r[m - (k1 - L1) + L2];
            const float u = fmaf(v1.x, v2.x, -(v1.y * v2.y));
            const float v = fmaf(v1.x, v2.y, v1.y * v2.x);
#pragma unroll
            for (int lu = 0; lu < NL; lu++) {
                const int l = LA + lu;
                if (l >= absm) {
                    const float C = g_cgs<L1, L2, LA, LB>.c[lu][m + l][k1];
                    if (C != 0.0f) {           // folds at compile time
                        aR[lu] = fmaf(C, u, aR[lu]);
                        aI[lu] = fmaf(C, v, aI[lu]);
                    }
                }
            }
        }
#pragma unroll
        for (int lu = 0; lu < NL; lu++) {
            const int l = LA + lu;
            if (l >= absm)
                sh[g_off<L1, L2, LA, LB>.sbase[lu] + t * (2 * l + 1) + (m + l)]
                    = make_float2(aR[lu], aI[lu]);
        }
    }
    __syncthreads();

    // TMA-engine copy-out: one bulk SMEM->GMEM copy per l-section, tagged
    // L2::evict_first (output is write-once-never-read; don't retain in L2).
    // Final wait uses .read semantics: only the SMEM source reads must finish
    // before the CTA may retire; grid completion guarantees global visibility.
    if (t == 0) {
        unsigned long long pol;
        asm("createpolicy.fractional.L2::evict_first.b64 %0, 1.0;" : "=l"(pol));
        asm volatile("fence.proxy.async.shared::cta;" ::: "memory");
#pragma unroll
        for (int lu = 0; lu < NL; lu++) {
            const int l = LA + lu, D = 2 * l + 1;
            float2* dst = out + g_off<L1, L2, LA, LB>.dbase[lu]
                        + (long)b * g_off<L1, L2, LA, LB>.bstr[lu];
            uint32_t saddr;
            asm("{ .reg .u64 tt; cvta.to.shared.u64 tt, %1; cvt.u32.u64 %0, tt; }"
                : "=r"(saddr)
                : "l"(sh + g_off<L1, L2, LA, LB>.sbase[lu]));
            asm volatile(
                "cp.async.bulk.global.shared::cta.bulk_group.L2::cache_hint "
                "[%0], [%1], %2, %3;"
                :: "l"((unsigned long long)(uintptr_t)dst),
                   "r"(saddr), "r"(2048 * D), "l"(pol)
                : "memory");
        }
        asm volatile("cp.async.bulk.commit_group;" ::: "memory");
        asm volatile("cp.async.bulk.wait_group.read 0;" ::: "memory");
    }
}

__global__ void __launch_bounds__(256, 4) cg_main_kernel(
    const float* __restrict__ a0, const float* __restrict__ a1,
    const float* __restrict__ a2, const float* __restrict__ a3,
    const float* __restrict__ a4, const float* __restrict__ a5,
    float2* __restrict__ out)
{
    __shared__ alignas(16) float2 sh[21 * 256];   // max sum(2l+1)=21 -> 43KB
    const int b = blockIdx.x;

    switch (blockIdx.y) {
#define GCASE(G,L1,L2,LA,LB)                                                  \
    case G:                                                                   \
        grp_body<L1, L2, LA, LB>((const float2*)a##L1, (const float2*)a##L2,  \
                                 out, b, sh);                                 \
        break;
    GROUPS(GCASE)
#undef GCASE
    default: break;
    }
}

// ---------------------------------------------------------------------------
// Host side
// ---------------------------------------------------------------------------
extern "C" void kernel_launch(void* const* d_in, const int* in_sizes, int n_in,
                              void* d_out, int out_size)
{
    (void)in_sizes; (void)n_in; (void)out_size;

    cg_main_kernel<<<dim3(256, NGRP), 256>>>(
        (const float*)d_in[0], (const float*)d_in[1], (const float*)d_in[2],
        (const float*)d_in[3], (const float*)d_in[4], (const float*)d_in[5],
        (float2*)d_out);
}